// round 15
// baseline (speedup 1.0000x reference)
#include <cuda_runtime.h>
#include <cstdint>

typedef unsigned long long ull;

// Problem constants
#define BB 128
#define SS 1024
#define FF 512
#define HH 32
#define GG 128              // 4*H
#define NTOK (BB*SS)        // 131072

// Scratch (device globals: allocation-free, graph-capturable)
__device__ __align__(16) float g_xg[(size_t)NTOK * GG];  // PERMUTED: [tok][4*j+gate]
__device__ __align__(16) float g_hs[(size_t)NTOK * HH];
__device__ __align__(16) float g_wxp[64 * GG];           // permuted Wx
__device__ __align__(16) float g_blp[GG];                // permuted bl

// ---------------------------------------------------------------------------
// helpers
// ---------------------------------------------------------------------------
__device__ __forceinline__ ull pk2(float lo, float hi) {
    ull r; asm("mov.b64 %0, {%1,%2};" : "=l"(r) : "f"(lo), "f"(hi)); return r;
}
__device__ __forceinline__ void upk2(ull v, float& lo, float& hi) {
    asm("mov.b64 {%0,%1}, %2;" : "=f"(lo), "=f"(hi) : "l"(v));
}
__device__ __forceinline__ void fma2(ull& d, ull a, ull b) {
    asm("fma.rn.f32x2 %0, %1, %2, %0;" : "+l"(d) : "l"(a), "l"(b));
}
__device__ __forceinline__ ull add2(ull a, ull b) {
    ull r; asm("add.rn.f32x2 %0, %1, %2;" : "=l"(r) : "l"(a), "l"(b)); return r;
}

// MUFU-based activations — used ONLY in the LSTM recurrence
__device__ __forceinline__ float sigf(float x) {
    return __fdividef(1.f, 1.f + __expf(-x));
}
__device__ __forceinline__ float tanhfast(float x) {
    return 2.f * __fdividef(1.f, 1.f + __expf(-2.f * x)) - 1.f;
}

// MUFU-free reciprocal: integer seed + 3 Newton steps
__device__ __forceinline__ float rcp_nr(float q) {
    float r = __uint_as_float(0x7EF311C3u - __float_as_uint(q));
    r = r * (2.0f - q * r);
    r = r * (2.0f - q * r);
    r = r * (2.0f - q * r);
    return r;
}
// MUFU-free tanh: rational poly, |err| ~1e-6, pure fma/alu pipe
__device__ __forceinline__ float tanh_poly(float x) {
    const float cl = 7.90531110763549805f;
    x = fminf(cl, fmaxf(-cl, x));
    float x2 = x * x;
    float p = fmaf(x2, -2.76076847742355e-16f, 2.00018790482477e-13f);
    p = fmaf(x2, p, -8.60467152213735e-11f);
    p = fmaf(x2, p,  5.12229709037114e-08f);
    p = fmaf(x2, p,  1.48572235717979e-05f);
    p = fmaf(x2, p,  6.37261928875436e-04f);
    p = fmaf(x2, p,  4.89352455891786e-03f);
    p = p * x;
    float q = fmaf(x2, 1.19825839466702e-06f, 1.18534705686654e-04f);
    q = fmaf(x2, q, 2.26843463243900e-03f);
    q = fmaf(x2, q, 4.89352518554385e-03f);
    return p * rcp_nr(q);
}

// ---------------------------------------------------------------------------
// K0: permute Wx[64,128] and bl[128]: wxp[k][4j+g] = Wx[k][32g+j]
// ---------------------------------------------------------------------------
__global__ void k_perm(const float* __restrict__ Wx, const float* __restrict__ bl)
{
    int t = threadIdx.x;          // 0..127  (= 4j+g)
    int j = t >> 2, g = t & 3;
    int kb = blockIdx.x;
    if (kb < 64) g_wxp[kb * GG + t] = Wx[kb * GG + 32 * g + j];
    else         g_blp[t] = bl[32 * g + j];
}

// ---------------------------------------------------------------------------
// K1: front MLP (R13 winner, unchanged).
// ---------------------------------------------------------------------------
__global__ __launch_bounds__(256, 2) void k_front(
    const float* __restrict__ x,  const float* __restrict__ W1, const float* __restrict__ b1,
    const float* __restrict__ W2, const float* __restrict__ b2)
{
    __shared__ __align__(16) float xs [64 * 68];   // x tile, K-chunk of 64
    __shared__ __align__(16) float h1s[64 * 36];   // tanh(x@W1+b1) [tok][k]
    __shared__ __align__(16) float h2t[64 * 68];   // tanh(h1@W2+b2) TRANSPOSED [k][tok]

    const int tid  = threadIdx.x;
    const int tok0 = blockIdx.x * 64;

    // ---- GEMM1: [64,512] @ [512,32] (scalar) ----
    const int c  = tid & 31;
    const int r8 = tid >> 5;
    float acc[8];
#pragma unroll
    for (int i = 0; i < 8; i++) acc[i] = 0.f;

    for (int kk = 0; kk < FF; kk += 64) {
        __syncthreads();
#pragma unroll
        for (int q = 0; q < 4; q++) {
            int idx  = tid + 256 * q;
            int trow = idx >> 4;
            int kq   = idx & 15;
            float4 v = *(const float4*)(x + (size_t)(tok0 + trow) * FF + kk + kq * 4);
            *(float4*)(xs + trow * 68 + kq * 4) = v;
        }
        __syncthreads();
#pragma unroll 4
        for (int k = 0; k < 64; k += 4) {
            float w0 = __ldg(W1 + (kk + k + 0) * 32 + c);
            float w1 = __ldg(W1 + (kk + k + 1) * 32 + c);
            float w2 = __ldg(W1 + (kk + k + 2) * 32 + c);
            float w3 = __ldg(W1 + (kk + k + 3) * 32 + c);
#pragma unroll
            for (int i = 0; i < 8; i++) {
                float4 xv = *(const float4*)(xs + (r8 * 8 + i) * 68 + k);
                acc[i] = fmaf(xv.w, w3, fmaf(xv.z, w2, fmaf(xv.y, w1, fmaf(xv.x, w0, acc[i]))));
            }
        }
    }
    {
        float bb = __ldg(b1 + c);
#pragma unroll
        for (int i = 0; i < 8; i++)
            h1s[(r8 * 8 + i) * 36 + c] = tanh_poly(acc[i] + bb);
    }
    __syncthreads();

    // ---- GEMM2: [64,32] @ [32,64] (scalar) -> h2t TRANSPOSED ----
    {
        const int c2 = tid & 63;
        const int rg = tid >> 6;
        float a2[16];
#pragma unroll
        for (int i = 0; i < 16; i++) a2[i] = 0.f;
#pragma unroll
        for (int k = 0; k < 32; k += 4) {
            float w0 = __ldg(W2 + (k + 0) * 64 + c2);
            float w1 = __ldg(W2 + (k + 1) * 64 + c2);
            float w2 = __ldg(W2 + (k + 2) * 64 + c2);
            float w3 = __ldg(W2 + (k + 3) * 64 + c2);
#pragma unroll
            for (int i = 0; i < 16; i++) {
                float4 xv = *(const float4*)(h1s + (rg * 16 + i) * 36 + k);
                a2[i] = fmaf(xv.w, w3, fmaf(xv.z, w2, fmaf(xv.y, w1, fmaf(xv.x, w0, a2[i]))));
            }
        }
        float bb = __ldg(b2 + c2);
#pragma unroll
        for (int i = 0; i < 16; i++)
            h2t[c2 * 68 + rg * 16 + i] = tanh_poly(a2[i] + bb);   // transposed write
    }
    __syncthreads();

    // ---- GEMM3 (f32x2 token-packed): [64,64] @ wxp[64,128] + blp -> g_xg ----
    {
        const int lane = tid & 31;      // cols 4*lane .. 4*lane+3 (permuted col space)
        const int wrp  = tid >> 5;      // token octet: tokens wrp*8 .. wrp*8+7
        ull a[4][4];                    // [tokpair][col]
#pragma unroll
        for (int tp = 0; tp < 4; tp++)
#pragma unroll
            for (int cc = 0; cc < 4; cc++) a[tp][cc] = 0ull;

#pragma unroll 4
        for (int k = 0; k < 64; k++) {
            float4 t01 = *(const float4*)(h2t + k * 68 + wrp * 8);
            float4 t23 = *(const float4*)(h2t + k * 68 + wrp * 8 + 4);
            float4 w   = *(const float4*)(g_wxp + (size_t)k * GG + lane * 4);
            ull xv[4] = { pk2(t01.x, t01.y), pk2(t01.z, t01.w),
                          pk2(t23.x, t23.y), pk2(t23.z, t23.w) };
            ull w0 = pk2(w.x, w.x), w1 = pk2(w.y, w.y),
                w2 = pk2(w.z, w.z), w3 = pk2(w.w, w.w);
#pragma unroll
            for (int tp = 0; tp < 4; tp++) {
                fma2(a[tp][0], xv[tp], w0);
                fma2(a[tp][1], xv[tp], w1);
                fma2(a[tp][2], xv[tp], w2);
                fma2(a[tp][3], xv[tp], w3);
            }
        }
        float4 bb = *(const float4*)(g_blp + lane * 4);
#pragma unroll
        for (int tp = 0; tp < 4; tp++) {
            float v0l, v0h, v1l, v1h, v2l, v2h, v3l, v3h;
            upk2(a[tp][0], v0l, v0h); upk2(a[tp][1], v1l, v1h);
            upk2(a[tp][2], v2l, v2h); upk2(a[tp][3], v3l, v3h);
            int t0 = tok0 + wrp * 8 + 2 * tp;
            float4 o0 = { v0l + bb.x, v1l + bb.y, v2l + bb.z, v3l + bb.w };
            float4 o1 = { v0h + bb.x, v1h + bb.y, v2h + bb.z, v3h + bb.w };
            *(float4*)(g_xg + (size_t)t0 * GG + lane * 4)       = o0;
            *(float4*)(g_xg + (size_t)(t0 + 1) * GG + lane * 4) = o1;
        }
    }
}

// ---------------------------------------------------------------------------
// K2: LSTM scan — FOUR warps per batch, k-dimension split 8 per warp.
// grid = 128, block = 128. Thread j of warp w: unit j, k-range [8w, 8w+8).
// Per warp per step: 8 shfl + 16 fma2 (vs 32 shfl + 64 fma2 on one warp).
// Partials exchanged via double-buffered smem + ONE __syncthreads per step;
// all warps redundantly compute the identical (c,h) update so h_j stays in
// thread j of every warp (no h re-broadcast). Warp 0 owns xg prefetch + store.
// ---------------------------------------------------------------------------
__global__ __launch_bounds__(128, 1) void k_lstm(const float* __restrict__ Wh)
{
    // partials: [buf][warp][thread] -> (aif, ago) as 16 bytes
    __shared__ __align__(16) ull part[2][4][32][2];

    const int b   = blockIdx.x;
    const int tid = threadIdx.x;
    const int w   = tid >> 5;
    const int j   = tid & 31;
    const int k0  = w * 8;

    // 8 Wh column-pairs for this warp's k-range (32 regs)
    ull wif[8], wgo[8];
#pragma unroll
    for (int kk = 0; kk < 8; kk++) {
        const float* row = Wh + (size_t)(k0 + kk) * GG;
        wif[kk] = pk2(__ldg(row + j),      __ldg(row + 32 + j));
        wgo[kk] = pk2(__ldg(row + 64 + j), __ldg(row + 96 + j));
    }

    const float4* xgb = reinterpret_cast<const float4*>(g_xg) + (size_t)b * SS * 32 + j;
    float* hsb = g_hs + (size_t)b * SS * HH + j;

    float c = 0.f, h = 0.f;

    // warp 0 only: xg prefetch ring depth 4
    float4 pf[4];
    if (w == 0) {
#pragma unroll
        for (int q = 0; q < 4; q++) pf[q] = __ldg(xgb + (size_t)q * 32);
    }

    for (int t = 0; t < SS; t++) {
        ull aif, ago;
        if (w == 0) {
            float4 g4 = pf[t & 3];
            int tn = (t + 4 < SS) ? (t + 4) : (SS - 1);
            pf[t & 3] = __ldg(xgb + (size_t)tn * 32);
            aif = pk2(g4.x, g4.y);
            ago = pk2(g4.z, g4.w);
        } else {
            aif = 0ull;
            ago = 0ull;
        }

        // partial recurrence over this warp's 8 k's (h_k from own registers)
#pragma unroll
        for (int kk = 0; kk < 8; kk += 2) {
            float h0 = __shfl_sync(0xffffffffu, h, k0 + kk);
            float h1 = __shfl_sync(0xffffffffu, h, k0 + kk + 1);
            ull d0 = pk2(h0, h0), d1 = pk2(h1, h1);
            fma2(aif, d0, wif[kk]);     fma2(ago, d0, wgo[kk]);
            fma2(aif, d1, wif[kk + 1]); fma2(ago, d1, wgo[kk + 1]);
        }

        // publish partials (STS.128), one barrier, then everyone sums all 4
        {
            float a0, a1, g0, g1;
            upk2(aif, a0, a1); upk2(ago, g0, g1);
            float4 pv = { a0, a1, g0, g1 };
            *(float4*)&part[t & 1][w][j][0] = pv;
        }
        __syncthreads();

        float4 p0 = *(const float4*)&part[t & 1][0][j][0];
        float4 p1 = *(const float4*)&part[t & 1][1][j][0];
        float4 p2 = *(const float4*)&part[t & 1][2][j][0];
        float4 p3 = *(const float4*)&part[t & 1][3][j][0];
        ull sif = add2(add2(pk2(p0.x, p0.y), pk2(p1.x, p1.y)),
                       add2(pk2(p2.x, p2.y), pk2(p3.x, p3.y)));
        ull sgo = add2(add2(pk2(p0.z, p0.w), pk2(p1.z, p1.w)),
                       add2(pk2(p2.z, p2.w), pk2(p3.z, p3.w)));

        float ai, af, ag, ao;
        upk2(sif, ai, af); upk2(sgo, ag, ao);

        float ig = sigf(ai), fg = sigf(af), og = sigf(ao);
        c = fg * c + ig * tanhfast(ag);
        h = og * tanhfast(c);

        if (w == 0)
            hsb[(size_t)t * HH] = h;
    }
}

// ---------------------------------------------------------------------------
// K3: back MLP (R13 winner, unchanged — measured ~211µs).
// ---------------------------------------------------------------------------
__global__ __launch_bounds__(256, 2) void k_back(
    const float* __restrict__ W3, const float* __restrict__ b3,
    const float* __restrict__ W4, const float* __restrict__ b4,
    float* __restrict__ out)
{
    __shared__ __align__(16) float hss[64 * 36];   // hs tile [tok][k]
    __shared__ __align__(16) float h3t[64 * 68];   // tanh(hs@W3+b3) TRANSPOSED [k][tok]

    const int tid  = threadIdx.x;
    const int tok0 = blockIdx.x * 64;

    // stage hs tile (64x32)
#pragma unroll
    for (int q = 0; q < 2; q++) {
        int idx = tid + 256 * q;          // 0..511
        int trow = idx >> 3, kq = idx & 7;
        float4 v = *(const float4*)(g_hs + (size_t)(tok0 + trow) * HH + kq * 4);
        *(float4*)(hss + trow * 36 + kq * 4) = v;
    }
    __syncthreads();

    // ---- GEMM W3: [64,32]@[32,64] (scalar) -> h3t TRANSPOSED ----
    {
        const int c2 = tid & 63;
        const int rg = tid >> 6;
        float a2[16];
#pragma unroll
        for (int i = 0; i < 16; i++) a2[i] = 0.f;
#pragma unroll
        for (int k = 0; k < 32; k += 4) {
            float w0 = __ldg(W3 + (k + 0) * 64 + c2);
            float w1 = __ldg(W3 + (k + 1) * 64 + c2);
            float w2 = __ldg(W3 + (k + 2) * 64 + c2);
            float w3 = __ldg(W3 + (k + 3) * 64 + c2);
#pragma unroll
            for (int i = 0; i < 16; i++) {
                float4 xv = *(const float4*)(hss + (rg * 16 + i) * 36 + k);
                a2[i] = fmaf(xv.w, w3, fmaf(xv.z, w2, fmaf(xv.y, w1, fmaf(xv.x, w0, a2[i]))));
            }
        }
        float bb = __ldg(b3 + c2);
#pragma unroll
        for (int i = 0; i < 16; i++)
            h3t[c2 * 68 + rg * 16 + i] = tanh_poly(a2[i] + bb);   // transposed write
    }
    __syncthreads();

    // ---- GEMM W4 (f32x2 token-packed): [64,64]@[64,512], 4 chunks of 128 cols ----
    const int lane = tid & 31;     // cols nc + 4*lane .. +3
    const int wrp  = tid >> 5;     // token octet
#pragma unroll 1
    for (int nc = 0; nc < 512; nc += 128) {
        ull a[4][4];
#pragma unroll
        for (int tp = 0; tp < 4; tp++)
#pragma unroll
            for (int cc = 0; cc < 4; cc++) a[tp][cc] = 0ull;

#pragma unroll 4
        for (int k = 0; k < 64; k++) {
            float4 t01 = *(const float4*)(h3t + k * 68 + wrp * 8);
            float4 t23 = *(const float4*)(h3t + k * 68 + wrp * 8 + 4);
            float4 w   = *(const float4*)(W4 + (size_t)k * 512 + nc + lane * 4);
            ull xv[4] = { pk2(t01.x, t01.y), pk2(t01.z, t01.w),
                          pk2(t23.x, t23.y), pk2(t23.z, t23.w) };
            ull w0 = pk2(w.x, w.x), w1 = pk2(w.y, w.y),
                w2 = pk2(w.z, w.z), w3 = pk2(w.w, w.w);
#pragma unroll
            for (int tp = 0; tp < 4; tp++) {
                fma2(a[tp][0], xv[tp], w0);
                fma2(a[tp][1], xv[tp], w1);
                fma2(a[tp][2], xv[tp], w2);
                fma2(a[tp][3], xv[tp], w3);
            }
        }
        float4 bb = *(const float4*)(b4 + nc + lane * 4);
#pragma unroll
        for (int tp = 0; tp < 4; tp++) {
            float v0l, v0h, v1l, v1h, v2l, v2h, v3l, v3h;
            upk2(a[tp][0], v0l, v0h); upk2(a[tp][1], v1l, v1h);
            upk2(a[tp][2], v2l, v2h); upk2(a[tp][3], v3l, v3h);
            int t0 = tok0 + wrp * 8 + 2 * tp;
            float4 o0 = { v0l + bb.x, v1l + bb.y, v2l + bb.z, v3l + bb.w };
            float4 o1 = { v0h + bb.x, v1h + bb.y, v2h + bb.z, v3h + bb.w };
            *(float4*)(out + (size_t)t0 * 512 + nc + lane * 4)       = o0;
            *(float4*)(out + (size_t)(t0 + 1) * 512 + nc + lane * 4) = o1;
        }
    }
}

// ---------------------------------------------------------------------------
extern "C" void kernel_launch(void* const* d_in, const int* in_sizes, int n_in,
                              void* d_out, int out_size)
{
    const float* x  = (const float*)d_in[0];
    const float* W1 = (const float*)d_in[1];
    const float* b1 = (const float*)d_in[2];
    const float* W2 = (const float*)d_in[3];
    const float* b2 = (const float*)d_in[4];
    const float* Wx = (const float*)d_in[5];
    const float* Wh = (const float*)d_in[6];
    const float* bl = (const float*)d_in[7];
    const float* W3 = (const float*)d_in[8];
    const float* b3 = (const float*)d_in[9];
    const float* W4 = (const float*)d_in[10];
    const float* b4 = (const float*)d_in[11];
    float* out = (float*)d_out;

    k_perm <<<65, 128>>>(Wx, bl);
    k_front<<<NTOK / 64, 256>>>(x, W1, b1, W2, b2);
    k_lstm <<<BB, 128>>>(Wh);
    k_back <<<NTOK / 64, 256>>>(W3, b3, W4, b4, out);
}

// round 17
// speedup vs baseline: 1.4989x; 1.4989x over previous
#include <cuda_runtime.h>
#include <cstdint>

typedef unsigned long long ull;

// Problem constants
#define BB 128
#define SS 1024
#define FF 512
#define HH 32
#define GG 128              // 4*H
#define NTOK (BB*SS)        // 131072

// Scratch (device globals: allocation-free, graph-capturable)
__device__ __align__(16) float g_xg[(size_t)NTOK * GG];  // PERMUTED: [tok][4*j+gate]
__device__ __align__(16) float g_hs[(size_t)NTOK * HH];
__device__ __align__(16) float g_wxp[64 * GG];           // permuted Wx
__device__ __align__(16) float g_blp[GG];                // permuted bl
__device__ __align__(16) ull   g_w1p[256 * 32];          // k-paired W1: [kp][c] = (W1[2kp][c], W1[2kp+1][c])

// ---------------------------------------------------------------------------
// helpers
// ---------------------------------------------------------------------------
__device__ __forceinline__ ull pk2(float lo, float hi) {
    ull r; asm("mov.b64 %0, {%1,%2};" : "=l"(r) : "f"(lo), "f"(hi)); return r;
}
__device__ __forceinline__ void upk2(ull v, float& lo, float& hi) {
    asm("mov.b64 {%0,%1}, %2;" : "=f"(lo), "=f"(hi) : "l"(v));
}
__device__ __forceinline__ void fma2(ull& d, ull a, ull b) {
    asm("fma.rn.f32x2 %0, %1, %2, %0;" : "+l"(d) : "l"(a), "l"(b));
}
__device__ __forceinline__ ull add2(ull a, ull b) {
    ull r; asm("add.rn.f32x2 %0, %1, %2;" : "=l"(r) : "l"(a), "l"(b)); return r;
}

// MUFU-based activations — used ONLY in the LSTM recurrence
__device__ __forceinline__ float sigf(float x) {
    return __fdividef(1.f, 1.f + __expf(-x));
}
__device__ __forceinline__ float tanhfast(float x) {
    return 2.f * __fdividef(1.f, 1.f + __expf(-2.f * x)) - 1.f;
}

// MUFU-free reciprocal: integer seed + 3 Newton steps
__device__ __forceinline__ float rcp_nr(float q) {
    float r = __uint_as_float(0x7EF311C3u - __float_as_uint(q));
    r = r * (2.0f - q * r);
    r = r * (2.0f - q * r);
    r = r * (2.0f - q * r);
    return r;
}
// MUFU-free tanh: rational poly, |err| ~1e-6, pure fma/alu pipe
__device__ __forceinline__ float tanh_poly(float x) {
    const float cl = 7.90531110763549805f;
    x = fminf(cl, fmaxf(-cl, x));
    float x2 = x * x;
    float p = fmaf(x2, -2.76076847742355e-16f, 2.00018790482477e-13f);
    p = fmaf(x2, p, -8.60467152213735e-11f);
    p = fmaf(x2, p,  5.12229709037114e-08f);
    p = fmaf(x2, p,  1.48572235717979e-05f);
    p = fmaf(x2, p,  6.37261928875436e-04f);
    p = fmaf(x2, p,  4.89352455891786e-03f);
    p = p * x;
    float q = fmaf(x2, 1.19825839466702e-06f, 1.18534705686654e-04f);
    q = fmaf(x2, q, 2.26843463243900e-03f);
    q = fmaf(x2, q, 4.89352518554385e-03f);
    return p * rcp_nr(q);
}

// ---------------------------------------------------------------------------
// K0: permute Wx/bl (blocks 0..64) and build k-paired W1 (blocks 65..128).
// ---------------------------------------------------------------------------
__global__ void k_perm(const float* __restrict__ Wx, const float* __restrict__ bl,
                       const float* __restrict__ W1)
{
    int t  = threadIdx.x;          // 0..127
    int kb = blockIdx.x;
    if (kb < 64) {
        int j = t >> 2, g = t & 3;
        g_wxp[kb * GG + t] = Wx[kb * GG + 32 * g + j];
    } else if (kb == 64) {
        int j = t >> 2, g = t & 3;
        g_blp[t] = bl[32 * g + j];
    } else {
        int idx = (kb - 65) * 128 + t;      // 0..8191
        int kp = idx >> 5, c = idx & 31;
        g_w1p[kp * 32 + c] = pk2(W1[(2 * kp) * 32 + c], W1[(2 * kp + 1) * 32 + c]);
    }
}

// ---------------------------------------------------------------------------
// K1: front MLP.  GEMM1 now k-pair-packed f32x2 (this round's change);
// GEMM2 scalar -> h2t TRANSPOSED; GEMM3 token-packed f32x2 (R13).
// CTA: 256 threads, 64 tokens. grid = 2048.
// ---------------------------------------------------------------------------
__global__ __launch_bounds__(256, 2) void k_front(
    const float* __restrict__ x,  const float* __restrict__ b1,
    const float* __restrict__ W2, const float* __restrict__ b2)
{
    __shared__ __align__(16) float xs [64 * 68];   // x tile, K-chunk of 64
    __shared__ __align__(16) float h1s[64 * 36];   // tanh(x@W1+b1) [tok][k]
    __shared__ __align__(16) float h2t[64 * 68];   // tanh(h1@W2+b2) TRANSPOSED [k][tok]

    const int tid  = threadIdx.x;
    const int tok0 = blockIdx.x * 64;

    // ---- GEMM1 (k-pair f32x2): [64,512] @ [512,32] ----
    const int c  = tid & 31;
    const int r8 = tid >> 5;
    ull acc2[8];
#pragma unroll
    for (int i = 0; i < 8; i++) acc2[i] = 0ull;

    for (int kk = 0; kk < FF; kk += 64) {
        __syncthreads();
#pragma unroll
        for (int q = 0; q < 4; q++) {
            int idx  = tid + 256 * q;
            int trow = idx >> 4;
            int kq   = idx & 15;
            float4 v = *(const float4*)(x + (size_t)(tok0 + trow) * FF + kk + kq * 4);
            *(float4*)(xs + trow * 68 + kq * 4) = v;
        }
        __syncthreads();
        const int kp0 = kk >> 1;               // base k-pair index of this chunk
#pragma unroll 4
        for (int kp = 0; kp < 32; kp += 2) {   // 2 k-pairs = 4 k per iter
            ull w0 = g_w1p[(kp0 + kp) * 32 + c];        // LDG.64 (coalesced)
            ull w1 = g_w1p[(kp0 + kp + 1) * 32 + c];
#pragma unroll
            for (int i = 0; i < 8; i++) {
                // floats [2kp .. 2kp+3] = k-pairs kp, kp+1 (16B aligned, broadcast)
                longlong2 xv = *(const longlong2*)(xs + (r8 * 8 + i) * 68 + 2 * kp);
                fma2(acc2[i], (ull)xv.x, w0);
                fma2(acc2[i], (ull)xv.y, w1);
            }
        }
    }
    {
        float bb = __ldg(b1 + c);
#pragma unroll
        for (int i = 0; i < 8; i++) {
            float e, o;
            upk2(acc2[i], e, o);               // even-k / odd-k partial sums
            h1s[(r8 * 8 + i) * 36 + c] = tanh_poly(e + o + bb);
        }
    }
    __syncthreads();

    // ---- GEMM2: [64,32] @ [32,64] (scalar) -> h2t TRANSPOSED ----
    {
        const int c2 = tid & 63;
        const int rg = tid >> 6;
        float a2[16];
#pragma unroll
        for (int i = 0; i < 16; i++) a2[i] = 0.f;
#pragma unroll
        for (int k = 0; k < 32; k += 4) {
            float w0 = __ldg(W2 + (k + 0) * 64 + c2);
            float w1 = __ldg(W2 + (k + 1) * 64 + c2);
            float w2 = __ldg(W2 + (k + 2) * 64 + c2);
            float w3 = __ldg(W2 + (k + 3) * 64 + c2);
#pragma unroll
            for (int i = 0; i < 16; i++) {
                float4 xv = *(const float4*)(h1s + (rg * 16 + i) * 36 + k);
                a2[i] = fmaf(xv.w, w3, fmaf(xv.z, w2, fmaf(xv.y, w1, fmaf(xv.x, w0, a2[i]))));
            }
        }
        float bb = __ldg(b2 + c2);
#pragma unroll
        for (int i = 0; i < 16; i++)
            h2t[c2 * 68 + rg * 16 + i] = tanh_poly(a2[i] + bb);   // transposed write
    }
    __syncthreads();

    // ---- GEMM3 (f32x2 token-packed): [64,64] @ wxp[64,128] + blp -> g_xg ----
    {
        const int lane = tid & 31;      // cols 4*lane .. 4*lane+3 (permuted col space)
        const int wrp  = tid >> 5;      // token octet: tokens wrp*8 .. wrp*8+7
        ull a[4][4];                    // [tokpair][col]
#pragma unroll
        for (int tp = 0; tp < 4; tp++)
#pragma unroll
            for (int cc = 0; cc < 4; cc++) a[tp][cc] = 0ull;

#pragma unroll 4
        for (int k = 0; k < 64; k++) {
            float4 t01 = *(const float4*)(h2t + k * 68 + wrp * 8);
            float4 t23 = *(const float4*)(h2t + k * 68 + wrp * 8 + 4);
            float4 w   = *(const float4*)(g_wxp + (size_t)k * GG + lane * 4);
            ull xv[4] = { pk2(t01.x, t01.y), pk2(t01.z, t01.w),
                          pk2(t23.x, t23.y), pk2(t23.z, t23.w) };
            ull w0 = pk2(w.x, w.x), w1 = pk2(w.y, w.y),
                w2 = pk2(w.z, w.z), w3 = pk2(w.w, w.w);
#pragma unroll
            for (int tp = 0; tp < 4; tp++) {
                fma2(a[tp][0], xv[tp], w0);
                fma2(a[tp][1], xv[tp], w1);
                fma2(a[tp][2], xv[tp], w2);
                fma2(a[tp][3], xv[tp], w3);
            }
        }
        float4 bb = *(const float4*)(g_blp + lane * 4);
#pragma unroll
        for (int tp = 0; tp < 4; tp++) {
            float v0l, v0h, v1l, v1h, v2l, v2h, v3l, v3h;
            upk2(a[tp][0], v0l, v0h); upk2(a[tp][1], v1l, v1h);
            upk2(a[tp][2], v2l, v2h); upk2(a[tp][3], v3l, v3h);
            int t0 = tok0 + wrp * 8 + 2 * tp;
            float4 o0 = { v0l + bb.x, v1l + bb.y, v2l + bb.z, v3l + bb.w };
            float4 o1 = { v0h + bb.x, v1h + bb.y, v2h + bb.z, v3h + bb.w };
            *(float4*)(g_xg + (size_t)t0 * GG + lane * 4)       = o0;
            *(float4*)(g_xg + (size_t)(t0 + 1) * GG + lane * 4) = o1;
        }
    }
}

// ---------------------------------------------------------------------------
// K2: LSTM scan (R8/R13 shfl version — confirmed local optimum).
// One warp per batch (grid=128, block=32). Thread j = unit j.
// ---------------------------------------------------------------------------
__global__ __launch_bounds__(32, 1) void k_lstm(const float* __restrict__ Wh)
{
    const int b = blockIdx.x;
    const int j = threadIdx.x;

    ull wif[HH], wgo[HH];
#pragma unroll
    for (int k = 0; k < HH; k++) {
        const float* row = Wh + k * GG;
        wif[k] = pk2(__ldg(row + j),      __ldg(row + 32 + j));
        wgo[k] = pk2(__ldg(row + 64 + j), __ldg(row + 96 + j));
    }

    const float4* xgb = reinterpret_cast<const float4*>(g_xg) + (size_t)b * SS * 32 + j;
    float* hsb = g_hs + (size_t)b * SS * HH + j;

    float c = 0.f, h = 0.f;
    float4 pf[4];
#pragma unroll
    for (int q = 0; q < 4; q++) pf[q] = __ldg(xgb + (size_t)q * 32);

#pragma unroll 4
    for (int t = 0; t < SS; t++) {
        float4 g4 = pf[t & 3];
        int tn = (t + 4 < SS) ? (t + 4) : (SS - 1);
        pf[t & 3] = __ldg(xgb + (size_t)tn * 32);

        ull aif0 = pk2(g4.x, g4.y), ago0 = pk2(g4.z, g4.w);
        ull aif1 = 0ull, ago1 = 0ull;

#pragma unroll
        for (int k = 0; k < HH; k += 2) {
            float h0 = __shfl_sync(0xffffffffu, h, k);
            float h1 = __shfl_sync(0xffffffffu, h, k + 1);
            ull d0 = pk2(h0, h0), d1 = pk2(h1, h1);
            fma2(aif0, d0, wif[k]);     fma2(ago0, d0, wgo[k]);
            fma2(aif1, d1, wif[k + 1]); fma2(ago1, d1, wgo[k + 1]);
        }
        ull aif = add2(aif0, aif1), ago = add2(ago0, ago1);
        float ai, af, ag, ao;
        upk2(aif, ai, af); upk2(ago, ag, ao);

        float ig = sigf(ai), fg = sigf(af), og = sigf(ao);
        c = fg * c + ig * tanhfast(ag);
        h = og * tanhfast(c);

        hsb[(size_t)t * HH] = h;
    }
}

// ---------------------------------------------------------------------------
// K3: back MLP (R13 winner, unchanged — measured ~211µs).
// ---------------------------------------------------------------------------
__global__ __launch_bounds__(256, 2) void k_back(
    const float* __restrict__ W3, const float* __restrict__ b3,
    const float* __restrict__ W4, const float* __restrict__ b4,
    float* __restrict__ out)
{
    __shared__ __align__(16) float hss[64 * 36];   // hs tile [tok][k]
    __shared__ __align__(16) float h3t[64 * 68];   // tanh(hs@W3+b3) TRANSPOSED [k][tok]

    const int tid  = threadIdx.x;
    const int tok0 = blockIdx.x * 64;

    // stage hs tile (64x32)
#pragma unroll
    for (int q = 0; q < 2; q++) {
        int idx = tid + 256 * q;          // 0..511
        int trow = idx >> 3, kq = idx & 7;
        float4 v = *(const float4*)(g_hs + (size_t)(tok0 + trow) * HH + kq * 4);
        *(float4*)(hss + trow * 36 + kq * 4) = v;
    }
    __syncthreads();

    // ---- GEMM W3: [64,32]@[32,64] (scalar) -> h3t TRANSPOSED ----
    {
        const int c2 = tid & 63;
        const int rg = tid >> 6;
        float a2[16];
#pragma unroll
        for (int i = 0; i < 16; i++) a2[i] = 0.f;
#pragma unroll
        for (int k = 0; k < 32; k += 4) {
            float w0 = __ldg(W3 + (k + 0) * 64 + c2);
            float w1 = __ldg(W3 + (k + 1) * 64 + c2);
            float w2 = __ldg(W3 + (k + 2) * 64 + c2);
            float w3 = __ldg(W3 + (k + 3) * 64 + c2);
#pragma unroll
            for (int i = 0; i < 16; i++) {
                float4 xv = *(const float4*)(hss + (rg * 16 + i) * 36 + k);
                a2[i] = fmaf(xv.w, w3, fmaf(xv.z, w2, fmaf(xv.y, w1, fmaf(xv.x, w0, a2[i]))));
            }
        }
        float bb = __ldg(b3 + c2);
#pragma unroll
        for (int i = 0; i < 16; i++)
            h3t[c2 * 68 + rg * 16 + i] = tanh_poly(a2[i] + bb);   // transposed write
    }
    __syncthreads();

    // ---- GEMM W4 (f32x2 token-packed): [64,64]@[64,512], 4 chunks of 128 cols ----
    const int lane = tid & 31;     // cols nc + 4*lane .. +3
    const int wrp  = tid >> 5;     // token octet
#pragma unroll 1
    for (int nc = 0; nc < 512; nc += 128) {
        ull a[4][4];
#pragma unroll
        for (int tp = 0; tp < 4; tp++)
#pragma unroll
            for (int cc = 0; cc < 4; cc++) a[tp][cc] = 0ull;

#pragma unroll 4
        for (int k = 0; k < 64; k++) {
            float4 t01 = *(const float4*)(h3t + k * 68 + wrp * 8);
            float4 t23 = *(const float4*)(h3t + k * 68 + wrp * 8 + 4);
            float4 w   = *(const float4*)(W4 + (size_t)k * 512 + nc + lane * 4);
            ull xv[4] = { pk2(t01.x, t01.y), pk2(t01.z, t01.w),
                          pk2(t23.x, t23.y), pk2(t23.z, t23.w) };
            ull w0 = pk2(w.x, w.x), w1 = pk2(w.y, w.y),
                w2 = pk2(w.z, w.z), w3 = pk2(w.w, w.w);
#pragma unroll
            for (int tp = 0; tp < 4; tp++) {
                fma2(a[tp][0], xv[tp], w0);
                fma2(a[tp][1], xv[tp], w1);
                fma2(a[tp][2], xv[tp], w2);
                fma2(a[tp][3], xv[tp], w3);
            }
        }
        float4 bb = *(const float4*)(b4 + nc + lane * 4);
#pragma unroll
        for (int tp = 0; tp < 4; tp++) {
            float v0l, v0h, v1l, v1h, v2l, v2h, v3l, v3h;
            upk2(a[tp][0], v0l, v0h); upk2(a[tp][1], v1l, v1h);
            upk2(a[tp][2], v2l, v2h); upk2(a[tp][3], v3l, v3h);
            int t0 = tok0 + wrp * 8 + 2 * tp;
            float4 o0 = { v0l + bb.x, v1l + bb.y, v2l + bb.z, v3l + bb.w };
            float4 o1 = { v0h + bb.x, v1h + bb.y, v2h + bb.z, v3h + bb.w };
            *(float4*)(out + (size_t)t0 * 512 + nc + lane * 4)       = o0;
            *(float4*)(out + (size_t)(t0 + 1) * 512 + nc + lane * 4) = o1;
        }
    }
}

// ---------------------------------------------------------------------------
extern "C" void kernel_launch(void* const* d_in, const int* in_sizes, int n_in,
                              void* d_out, int out_size)
{
    const float* x  = (const float*)d_in[0];
    const float* W1 = (const float*)d_in[1];
    const float* b1 = (const float*)d_in[2];
    const float* W2 = (const float*)d_in[3];
    const float* b2 = (const float*)d_in[4];
    const float* Wx = (const float*)d_in[5];
    const float* Wh = (const float*)d_in[6];
    const float* bl = (const float*)d_in[7];
    const float* W3 = (const float*)d_in[8];
    const float* b3 = (const float*)d_in[9];
    const float* W4 = (const float*)d_in[10];
    const float* b4 = (const float*)d_in[11];
    float* out = (float*)d_out;

    k_perm <<<129, 128>>>(Wx, bl, W1);
    k_front<<<NTOK / 64, 256>>>(x, b1, W2, b2);
    k_lstm <<<BB, 32>>>(Wh);
    k_back <<<NTOK / 64, 256>>>(W3, b3, W4, b4, out);
}